// round 12
// baseline (speedup 1.0000x reference)
#include <cuda_runtime.h>
#include <cuda_bf16.h>
#include <math.h>
#include <stdint.h>

#define S_LEN 2048
#define HIDDEN 2048
#define NH 32
#define NKV 8
#define HD 64
#define KV_W (NKV*HD)   // 512

// Q pre-scale: 1/sqrt(64) * log2(e)
#define QSCALE 0.18033688011112042f

// ---------------------------------------------------------------------------
// Device-global scratch
// ---------------------------------------------------------------------------
__device__ __nv_bfloat16 g_Xh[S_LEN * HIDDEN],   g_Xl[S_LEN * HIDDEN];
__device__ __nv_bfloat16 g_Wqh[HIDDEN * HIDDEN], g_Wql[HIDDEN * HIDDEN];
__device__ __nv_bfloat16 g_Wkh[KV_W * HIDDEN],   g_Wkl[KV_W * HIDDEN];
__device__ __nv_bfloat16 g_Wvh[KV_W * HIDDEN],   g_Wvl[KV_W * HIDDEN];
__device__ __nv_bfloat16 g_Woh[HIDDEN * HIDDEN], g_Wol[HIDDEN * HIDDEN];

__device__ __nv_bfloat16 g_qh[S_LEN * HIDDEN], g_ql[S_LEN * HIDDEN];
__device__ __nv_bfloat16 g_kh[S_LEN * KV_W],   g_kl[S_LEN * KV_W];
__device__ __nv_bfloat16 g_vh[S_LEN * KV_W],   g_vl[S_LEN * KV_W];
__device__ __nv_bfloat16 g_Ath[S_LEN * HIDDEN], g_Atl[S_LEN * HIDDEN];

// ---------------------------------------------------------------------------
// helpers
// ---------------------------------------------------------------------------
__device__ __forceinline__ uint32_t smem_u32(const void* p) {
    uint32_t a;
    asm("{ .reg .u64 t; cvta.to.shared.u64 t, %1; cvt.u32.u64 %0, t; }"
        : "=r"(a) : "l"(p));
    return a;
}
__device__ __forceinline__ void ldm_x4(uint32_t* r, uint32_t addr) {
    asm volatile("ldmatrix.sync.aligned.m8n8.x4.shared.b16 {%0,%1,%2,%3}, [%4];"
                 : "=r"(r[0]), "=r"(r[1]), "=r"(r[2]), "=r"(r[3]) : "r"(addr));
}
__device__ __forceinline__ void ldm_x2(uint32_t* r, uint32_t addr) {
    asm volatile("ldmatrix.sync.aligned.m8n8.x2.shared.b16 {%0,%1}, [%2];"
                 : "=r"(r[0]), "=r"(r[1]) : "r"(addr));
}
__device__ __forceinline__ void ldm_x2t(uint32_t* r, uint32_t addr) {
    asm volatile("ldmatrix.sync.aligned.m8n8.x2.trans.shared.b16 {%0,%1}, [%2];"
                 : "=r"(r[0]), "=r"(r[1]) : "r"(addr));
}
__device__ __forceinline__ void mma_bf16(float* d, const uint32_t* a, const uint32_t* b) {
    asm volatile(
        "mma.sync.aligned.m16n8k16.row.col.f32.bf16.bf16.f32 "
        "{%0,%1,%2,%3}, {%4,%5,%6,%7}, {%8,%9}, {%0,%1,%2,%3};"
        : "+f"(d[0]), "+f"(d[1]), "+f"(d[2]), "+f"(d[3])
        : "r"(a[0]), "r"(a[1]), "r"(a[2]), "r"(a[3]), "r"(b[0]), "r"(b[1]));
}
__device__ __forceinline__ void cp16(uint32_t saddr, const void* g) {
    asm volatile("cp.async.cg.shared.global [%0], [%1], 16;"
                 :: "r"(saddr), "l"(g) : "memory");
}
__device__ __forceinline__ float ex2(float x) {
    float r;
    asm("ex2.approx.ftz.f32 %0, %1;" : "=f"(r) : "f"(x));
    return r;
}
__device__ __forceinline__ void split2(float e0, float e1,
                                       uint32_t& hp_u, uint32_t& lp_u) {
    __nv_bfloat162 hp = __float22bfloat162_rn(make_float2(e0, e1));
    float h0 = __low2float(hp), h1 = __high2float(hp);
    __nv_bfloat162 lp = __float22bfloat162_rn(make_float2(e0 - h0, e1 - h1));
    hp_u = *reinterpret_cast<uint32_t*>(&hp);
    lp_u = *reinterpret_cast<uint32_t*>(&lp);
}

// ---------------------------------------------------------------------------
// Fused fp32 -> bf16 hi/lo split (one launch)
// ---------------------------------------------------------------------------
__global__ __launch_bounds__(256) void cvt_all(
    const float* __restrict__ X,  const float* __restrict__ Wq,
    const float* __restrict__ Wk, const float* __restrict__ Wv,
    const float* __restrict__ Wo)
{
    int b = blockIdx.x;
    const float* src;
    __nv_bfloat16 *hi, *lo;
    int base;
    if (b < 4096)       { src = X;  hi = g_Xh;  lo = g_Xl;  base = b; }
    else if (b < 8192)  { src = Wq; hi = g_Wqh; lo = g_Wql; base = b - 4096; }
    else if (b < 9216)  { src = Wk; hi = g_Wkh; lo = g_Wkl; base = b - 8192; }
    else if (b < 10240) { src = Wv; hi = g_Wvh; lo = g_Wvl; base = b - 9216; }
    else                { src = Wo; hi = g_Woh; lo = g_Wol; base = b - 10240; }

    int i = (base * 256 + threadIdx.x) * 4;
    float4 v = *(const float4*)(src + i);
    uint32_t h01, l01, h23, l23;
    split2(v.x, v.y, h01, l01);
    split2(v.z, v.w, h23, l23);
    uint32_t* hp = (uint32_t*)(hi + i);
    uint32_t* lp = (uint32_t*)(lo + i);
    hp[0] = h01; hp[1] = h23;
    lp[0] = l01; lp[1] = l23;
}

// ---------------------------------------------------------------------------
// Pipelined GEMM: BK=64, 3-stage cp.async, SW128 XOR, 512 threads (16 warps).
// Warp grid 4(M) x 4(N); warp tile 32x32; acc[2][4][4].
// ---------------------------------------------------------------------------
#define TILEB 16384
#define STAGEB 65536
#define GEMM_SMEM (3 * STAGEB)

extern __shared__ char dyn_smem[];

__device__ __forceinline__ void gemm_core(
    const __nv_bfloat16* __restrict__ gA0, const __nv_bfloat16* __restrict__ gA1,
    const __nv_bfloat16* __restrict__ gB0, const __nv_bfloat16* __restrict__ gB1,
    int K, uint32_t smb, float (&acc)[2][4][4])
{
    const int tid = threadIdx.x;
    const int wid = tid >> 5;
    const int lane = tid & 31;
    const int wm = wid >> 2;       // 0..3 (M)
    const int wn = wid & 3;        // 0..3 (N)

    const __nv_bfloat16* gT[4] = { gA0, gA1, gB0, gB1 };
    const int ldRow = tid >> 3;    // 0..63 (+64 with p)
    const int ldC   = tid & 7;
    const int nk = K / 64;

    auto issue = [&](int kc, int stg) {
        uint32_t sb = smb + stg * STAGEB;
#pragma unroll
        for (int t = 0; t < 4; t++) {
#pragma unroll
            for (int p = 0; p < 2; p++) {
                int row = ldRow + p * 64;
                int sw = ldC ^ (row & 7);
                cp16(sb + t * TILEB + row * 128 + sw * 16,
                     gT[t] + (size_t)row * K + kc * 64 + ldC * 8);
            }
        }
        asm volatile("cp.async.commit_group;" ::: "memory");
    };

    issue(0, 0);
    issue(1, 1);

    for (int kc = 0; kc < nk; kc++) {
        if (kc + 1 < nk)
            asm volatile("cp.async.wait_group 1;" ::: "memory");
        else
            asm volatile("cp.async.wait_group 0;" ::: "memory");
        __syncthreads();
        if (kc + 2 < nk) issue(kc + 2, (kc + 2) % 3);

        const uint32_t sb = smb + (kc % 3) * STAGEB;
#pragma unroll
        for (int ks = 0; ks < 4; ks++) {
            uint32_t bH[4][2], bL[4][2];
#pragma unroll
            for (int nt = 0; nt < 4; nt++) {
                int row = wn * 32 + nt * 8 + (lane & 7);
                int ch = ks * 2 + ((lane >> 3) & 1);
                uint32_t ba = sb + 2 * TILEB + row * 128 + ((ch ^ (row & 7)) * 16);
                ldm_x2(bH[nt], ba);
                ldm_x2(bL[nt], ba + TILEB);
            }
#pragma unroll
            for (int mt = 0; mt < 2; mt++) {
                int row = wm * 32 + mt * 16 + (lane & 15);
                int ch = ks * 2 + ((lane >> 4) & 1);
                uint32_t aa = sb + row * 128 + ((ch ^ (row & 7)) * 16);
                uint32_t aH[4], aL[4];
                ldm_x4(aH, aa);
                ldm_x4(aL, aa + TILEB);
#pragma unroll
                for (int nt = 0; nt < 4; nt++) mma_bf16(acc[mt][nt], aH, bH[nt]);
#pragma unroll
                for (int nt = 0; nt < 4; nt++) mma_bf16(acc[mt][nt], aL, bH[nt]);
#pragma unroll
                for (int nt = 0; nt < 4; nt++) mma_bf16(acc[mt][nt], aH, bL[nt]);
            }
        }
    }
}

__device__ __forceinline__ void epi_split(
    float (&acc)[2][4][4], __nv_bfloat16* Ch, __nv_bfloat16* Cl,
    int r0, int c0, int N, float scale)
{
    const int lane = threadIdx.x & 31;
    const int wid = threadIdx.x >> 5;
    const int wm = wid >> 2, wn = wid & 3;
    const int cr = lane >> 2;
    const int cc = (lane & 3) * 2;
#pragma unroll
    for (int mt = 0; mt < 2; mt++) {
#pragma unroll
        for (int nt = 0; nt < 4; nt++) {
            size_t i0 = (size_t)(r0 + wm * 32 + mt * 16 + cr) * N
                      + c0 + wn * 32 + nt * 8 + cc;
            size_t i1 = i0 + 8 * (size_t)N;
#pragma unroll
            for (int half = 0; half < 2; half++) {
                size_t ix = half ? i1 : i0;
                float e0 = acc[mt][nt][half * 2 + 0] * scale;
                float e1 = acc[mt][nt][half * 2 + 1] * scale;
                uint32_t hp, lp;
                split2(e0, e1, hp, lp);
                *(uint32_t*)(Ch + ix) = hp;
                *(uint32_t*)(Cl + ix) = lp;
            }
        }
    }
}

__global__ __launch_bounds__(512, 1) void gemm_qkv()
{
    const uint32_t smb = smem_u32(dyn_smem);
    const int bx = blockIdx.x;
    const int r0 = blockIdx.y * 128;

    const __nv_bfloat16 *Bh, *Bl;
    __nv_bfloat16 *Ch, *Cl;
    int N, c0;
    float scale;
    if (bx < 16)      { Bh = g_Wqh; Bl = g_Wql; Ch = g_qh; Cl = g_ql; N = HIDDEN; c0 = bx * 128;       scale = QSCALE; }
    else if (bx < 20) { Bh = g_Wkh; Bl = g_Wkl; Ch = g_kh; Cl = g_kl; N = KV_W;  c0 = (bx - 16) * 128; scale = 1.f; }
    else              { Bh = g_Wvh; Bl = g_Wvl; Ch = g_vh; Cl = g_vl; N = KV_W;  c0 = (bx - 20) * 128; scale = 1.f; }

    float acc[2][4][4];
#pragma unroll
    for (int i = 0; i < 2; i++)
#pragma unroll
        for (int j = 0; j < 4; j++)
#pragma unroll
            for (int e = 0; e < 4; e++) acc[i][j][e] = 0.f;

    gemm_core(g_Xh + (size_t)r0 * HIDDEN, g_Xl + (size_t)r0 * HIDDEN,
              Bh + (size_t)c0 * HIDDEN, Bl + (size_t)c0 * HIDDEN,
              HIDDEN, smb, acc);
    epi_split(acc, Ch, Cl, r0, c0, N, scale);
}

__global__ __launch_bounds__(512, 1) void gemm_oproj(float* __restrict__ Cf)
{
    const uint32_t smb = smem_u32(dyn_smem);
    const int r0 = blockIdx.y * 128;
    const int c0 = blockIdx.x * 128;

    float acc[2][4][4];
#pragma unroll
    for (int i = 0; i < 2; i++)
#pragma unroll
        for (int j = 0; j < 4; j++)
#pragma unroll
            for (int e = 0; e < 4; e++) acc[i][j][e] = 0.f;

    gemm_core(g_Ath + (size_t)r0 * HIDDEN, g_Atl + (size_t)r0 * HIDDEN,
              g_Woh + (size_t)c0 * HIDDEN, g_Wol + (size_t)c0 * HIDDEN,
              HIDDEN, smb, acc);

    const int lane = threadIdx.x & 31;
    const int wid = threadIdx.x >> 5;
    const int wm = wid >> 2, wn = wid & 3;
    const int cr = lane >> 2;
    const int cc = (lane & 3) * 2;
#pragma unroll
    for (int mt = 0; mt < 2; mt++) {
#pragma unroll
        for (int nt = 0; nt < 4; nt++) {
            float* base = Cf + (size_t)(r0 + wm * 32 + mt * 16 + cr) * HIDDEN
                             + c0 + wn * 32 + nt * 8 + cc;
            *(float2*)base = make_float2(acc[mt][nt][0], acc[mt][nt][1]);
            *(float2*)(base + 8 * (size_t)HIDDEN) =
                make_float2(acc[mt][nt][2], acc[mt][nt][3]);
        }
    }
}

// ---------------------------------------------------------------------------
// Flash attention (R11, unchanged): cp.async K/V, base-2 softmax, pre-scaled Q
// ---------------------------------------------------------------------------
#define SROW 72
#define QTILE 9216
#define KVTILE 4608
#define KVSTAGE 18432
#define FA_SMEM (55296 * 2)

__global__ __launch_bounds__(256, 1) void flash_attn_mma(
    const __nv_bfloat16* __restrict__ Qh_g, const __nv_bfloat16* __restrict__ Ql_g,
    const __nv_bfloat16* __restrict__ Kh_g, const __nv_bfloat16* __restrict__ Kl_g,
    const __nv_bfloat16* __restrict__ Vh_g, const __nv_bfloat16* __restrict__ Vl_g,
    __nv_bfloat16* __restrict__ Oh_g, __nv_bfloat16* __restrict__ Ol_g)
{
    __nv_bfloat16* sm = (__nv_bfloat16*)dyn_smem;
    const uint32_t smb = smem_u32(sm);

    const int tid  = threadIdx.x;
    const int wid  = tid >> 5;
    const int lane = tid & 31;
    const int qb = (int)gridDim.x - 1 - (int)blockIdx.x;
    const int hh = blockIdx.y;
    const int q0 = qb * 128;
    const int kvoff = (hh >> 2) * HD;

    const __nv_bfloat16* kvsrc[4] = { Kh_g, Kl_g, Vh_g, Vl_g };

    auto issue_kv = [&](int jb) {
        const int k0 = jb * 64;
        const uint32_t sb = smb + (uint32_t)(KVSTAGE + (jb & 1) * KVSTAGE) * 2;
#pragma unroll
        for (int p = 0; p < 8; p++) {
            int idx = tid + p * 256;
            int t = idx >> 9;
            int rem = idx & 511;
            int r = rem >> 3;
            int c = rem & 7;
            cp16(sb + (uint32_t)(t * KVTILE + r * SROW + c * 8) * 2,
                 kvsrc[t] + (size_t)(k0 + r) * KV_W + kvoff + c * 8);
        }
        asm volatile("cp.async.commit_group;" ::: "memory");
    };

#pragma unroll
    for (int p = 0; p < 8; p++) {
        int idx = tid + p * 256;
        int t = idx >> 10;
        int rem = idx & 1023;
        int r = rem >> 3;
        int c = rem & 7;
        const __nv_bfloat16* src = (t ? Ql_g : Qh_g) +
            (size_t)(q0 + r) * HIDDEN + hh * HD + c * 8;
        uint4 d = *(const uint4*)src;
        *(uint4*)(sm + (t ? QTILE : 0) + r * SROW + c * 8) = d;
    }

    float o[8][4];
#pragma unroll
    for (int nt = 0; nt < 8; nt++)
#pragma unroll
        for (int e = 0; e < 4; e++) o[nt][e] = 0.f;
    float m0 = -1e30f, m1 = -1e30f, l0 = 0.f, l1 = 0.f;

    const int cr = lane >> 2;
    const int cc = (lane & 3) * 2;
    const int row0 = q0 + wid * 16 + cr;
    const int row1 = row0 + 8;

    const uint32_t aHq = smb + (uint32_t)(
        (wid * 16 + (lane & 15)) * SROW + ((lane >> 4) & 1) * 8) * 2;
    const uint32_t aLq = aHq + (uint32_t)QTILE * 2;
    const uint32_t bKoff = (uint32_t)((lane & 7) * SROW + ((lane >> 3) & 1) * 8) * 2;
    const uint32_t bVoff = (uint32_t)(((lane & 7) + ((lane >> 3) & 1) * 8) * SROW) * 2;

    const int nkv = 2 * qb + 2;
    issue_kv(0);
    issue_kv(1);

    for (int jb = 0; jb < nkv; jb++) {
        const int k0 = jb * 64;
        if (jb + 1 < nkv)
            asm volatile("cp.async.wait_group 1;" ::: "memory");
        else
            asm volatile("cp.async.wait_group 0;" ::: "memory");
        __syncthreads();

        const uint32_t stb = smb + (uint32_t)(KVSTAGE + (jb & 1) * KVSTAGE) * 2;
        const uint32_t bK = stb + bKoff;
        const uint32_t bV = stb + (uint32_t)(2 * KVTILE) * 2 + bVoff;

        float s[8][4];
#pragma unroll
        for (int nt = 0; nt < 8; nt++)
#pragma unroll
            for (int e = 0; e < 4; e++) s[nt][e] = 0.f;

#pragma unroll
        for (int ks = 0; ks < 4; ks++) {
            uint32_t aH[4], aL[4];
            ldm_x4(aH, aHq + ks * 32);
            ldm_x4(aL, aLq + ks * 32);
#pragma unroll
            for (int nt = 0; nt < 8; nt++) {
                uint32_t bh[2], bl[2];
                uint32_t ba = bK + (uint32_t)(nt * 8 * SROW) * 2 + ks * 32;
                ldm_x2(bh, ba);
                ldm_x2(bl, ba + (uint32_t)KVTILE * 2);
                mma_bf16(s[nt], aH, bh);
                mma_bf16(s[nt], aL, bh);
                mma_bf16(s[nt], aH, bl);
            }
        }

        if (k0 + 63 > q0) {
#pragma unroll
            for (int nt = 0; nt < 8; nt++) {
                int col = k0 + nt * 8 + cc;
                if (col > row0)     s[nt][0] = -1e30f;
                if (col + 1 > row0) s[nt][1] = -1e30f;
                if (col > row1)     s[nt][2] = -1e30f;
                if (col + 1 > row1) s[nt][3] = -1e30f;
            }
        }

        float mx0 = -1e30f, mx1 = -1e30f;
#pragma unroll
        for (int nt = 0; nt < 8; nt++) {
            mx0 = fmaxf(mx0, fmaxf(s[nt][0], s[nt][1]));
            mx1 = fmaxf(mx1, fmaxf(s[nt][2], s[nt][3]));
        }
        mx0 = fmaxf(mx0, __shfl_xor_sync(0xffffffffu, mx0, 1));
        mx0 = fmaxf(mx0, __shfl_xor_sync(0xffffffffu, mx0, 2));
        mx1 = fmaxf(mx1, __shfl_xor_sync(0xffffffffu, mx1, 1));
        mx1 = fmaxf(mx1, __shfl_xor_sync(0xffffffffu, mx1, 2));

        float m0n = fmaxf(m0, mx0);
        float m1n = fmaxf(m1, mx1);

        float sum0 = 0.f, sum1 = 0.f;
#pragma unroll
        for (int nt = 0; nt < 8; nt++) {
            s[nt][0] = ex2(s[nt][0] - m0n);
            s[nt][1] = ex2(s[nt][1] - m0n);
            s[nt][2] = ex2(s[nt][2] - m1n);
            s[nt][3] = ex2(s[nt][3] - m1n);
            sum0 += s[nt][0] + s[nt][1];
            sum1 += s[nt][2] + s[nt][3];
        }
        sum0 += __shfl_xor_sync(0xffffffffu, sum0, 1);
        sum0 += __shfl_xor_sync(0xffffffffu, sum0, 2);
        sum1 += __shfl_xor_sync(0xffffffffu, sum1, 1);
        sum1 += __shfl_xor_sync(0xffffffffu, sum1, 2);

        float sc0 = ex2(m0 - m0n);
        float sc1 = ex2(m1 - m1n);
        l0 = l0 * sc0 + sum0;
        l1 = l1 * sc1 + sum1;
        m0 = m0n; m1 = m1n;

#pragma unroll
        for (int nt = 0; nt < 8; nt++) {
            o[nt][0] *= sc0; o[nt][1] *= sc0;
            o[nt][2] *= sc1; o[nt][3] *= sc1;
        }

#pragma unroll
        for (int ks = 0; ks < 4; ks++) {
            uint32_t aP[4], aPl[4];
#pragma unroll
            for (int half = 0; half < 2; half++) {
                int nt = 2 * ks + half;
                split2(s[nt][0], s[nt][1], aP[half * 2 + 0], aPl[half * 2 + 0]);
                split2(s[nt][2], s[nt][3], aP[half * 2 + 1], aPl[half * 2 + 1]);
            }
#pragma unroll
            for (int nt = 0; nt < 8; nt++) {
                uint32_t bh[2], bl[2];
                uint32_t ba = bV + (uint32_t)(ks * 16 * SROW + nt * 8) * 2;
                ldm_x2t(bh, ba);
                ldm_x2t(bl, ba + (uint32_t)KVTILE * 2);
                mma_bf16(o[nt], aP,  bh);
                mma_bf16(o[nt], aPl, bh);
                mma_bf16(o[nt], aP,  bl);
            }
        }

        __syncthreads();
        if (jb + 2 < nkv) issue_kv(jb + 2);
    }

    float inv0 = 1.f / l0;
    float inv1 = 1.f / l1;
#pragma unroll
    for (int nt = 0; nt < 8; nt++) {
        size_t i0 = (size_t)row0 * HIDDEN + hh * HD + nt * 8 + cc;
        size_t i1 = (size_t)row1 * HIDDEN + hh * HD + nt * 8 + cc;
        uint32_t hp0, lp0, hp1, lp1;
        split2(o[nt][0] * inv0, o[nt][1] * inv0, hp0, lp0);
        split2(o[nt][2] * inv1, o[nt][3] * inv1, hp1, lp1);
        *(uint32_t*)(Oh_g + i0) = hp0;
        *(uint32_t*)(Oh_g + i1) = hp1;
        *(uint32_t*)(Ol_g + i0) = lp0;
        *(uint32_t*)(Ol_g + i1) = lp1;
    }
}

// ---------------------------------------------------------------------------
// kernel_launch
// ---------------------------------------------------------------------------
extern "C" void kernel_launch(void* const* d_in, const int* in_sizes, int n_in,
                              void* d_out, int out_size)
{
    const float* X  = (const float*)d_in[0];
    const float* Wq = (const float*)d_in[2];
    const float* Wk = (const float*)d_in[3];
    const float* Wv = (const float*)d_in[4];
    const float* Wo = (const float*)d_in[5];
    float* out = (float*)d_out;

    __nv_bfloat16 *qh, *ql, *kh, *kl, *vh, *vl, *Ath, *Atl;
    cudaGetSymbolAddress((void**)&qh, g_qh);   cudaGetSymbolAddress((void**)&ql, g_ql);
    cudaGetSymbolAddress((void**)&kh, g_kh);   cudaGetSymbolAddress((void**)&kl, g_kl);
    cudaGetSymbolAddress((void**)&vh, g_vh);   cudaGetSymbolAddress((void**)&vl, g_vl);
    cudaGetSymbolAddress((void**)&Ath, g_Ath); cudaGetSymbolAddress((void**)&Atl, g_Atl);

    cvt_all<<<14336, 256>>>(X, Wq, Wk, Wv, Wo);

    cudaFuncSetAttribute(gemm_qkv, cudaFuncAttributeMaxDynamicSharedMemorySize, GEMM_SMEM);
    cudaFuncSetAttribute(gemm_oproj, cudaFuncAttributeMaxDynamicSharedMemorySize, GEMM_SMEM);

    gemm_qkv<<<dim3(24, 16), 512, GEMM_SMEM>>>();

    cudaFuncSetAttribute(flash_attn_mma, cudaFuncAttributeMaxDynamicSharedMemorySize, FA_SMEM);
    flash_attn_mma<<<dim3(S_LEN / 128, NH), 256, FA_SMEM>>>(
        qh, ql, kh, kl, vh, vl, Ath, Atl);

    gemm_oproj<<<dim3(16, 16), 512, GEMM_SMEM>>>(out);
}

// round 13
// speedup vs baseline: 1.0167x; 1.0167x over previous
#include <cuda_runtime.h>
#include <cuda_bf16.h>
#include <math.h>
#include <stdint.h>

#define S_LEN 2048
#define HIDDEN 2048
#define NH 32
#define NKV 8
#define HD 64
#define KV_W (NKV*HD)   // 512

// Q pre-scale: 1/sqrt(64) * log2(e)
#define QSCALE 0.18033688011112042f

// ---------------------------------------------------------------------------
// Device-global scratch
// ---------------------------------------------------------------------------
__device__ __nv_bfloat16 g_Xh[S_LEN * HIDDEN],   g_Xl[S_LEN * HIDDEN];
__device__ __nv_bfloat16 g_Wqh[HIDDEN * HIDDEN], g_Wql[HIDDEN * HIDDEN];
__device__ __nv_bfloat16 g_Wkh[KV_W * HIDDEN],   g_Wkl[KV_W * HIDDEN];
__device__ __nv_bfloat16 g_Wvh[KV_W * HIDDEN],   g_Wvl[KV_W * HIDDEN];
__device__ __nv_bfloat16 g_Woh[HIDDEN * HIDDEN], g_Wol[HIDDEN * HIDDEN];

__device__ __nv_bfloat16 g_qh[S_LEN * HIDDEN], g_ql[S_LEN * HIDDEN];
__device__ __nv_bfloat16 g_kh[S_LEN * KV_W],   g_kl[S_LEN * KV_W];
__device__ __nv_bfloat16 g_vh[S_LEN * KV_W],   g_vl[S_LEN * KV_W];
__device__ __nv_bfloat16 g_Ath[S_LEN * HIDDEN], g_Atl[S_LEN * HIDDEN];

// ---------------------------------------------------------------------------
// helpers
// ---------------------------------------------------------------------------
__device__ __forceinline__ uint32_t smem_u32(const void* p) {
    uint32_t a;
    asm("{ .reg .u64 t; cvta.to.shared.u64 t, %1; cvt.u32.u64 %0, t; }"
        : "=r"(a) : "l"(p));
    return a;
}
__device__ __forceinline__ void ldm_x4(uint32_t* r, uint32_t addr) {
    asm volatile("ldmatrix.sync.aligned.m8n8.x4.shared.b16 {%0,%1,%2,%3}, [%4];"
                 : "=r"(r[0]), "=r"(r[1]), "=r"(r[2]), "=r"(r[3]) : "r"(addr));
}
__device__ __forceinline__ void ldm_x2(uint32_t* r, uint32_t addr) {
    asm volatile("ldmatrix.sync.aligned.m8n8.x2.shared.b16 {%0,%1}, [%2];"
                 : "=r"(r[0]), "=r"(r[1]) : "r"(addr));
}
__device__ __forceinline__ void ldm_x2t(uint32_t* r, uint32_t addr) {
    asm volatile("ldmatrix.sync.aligned.m8n8.x2.trans.shared.b16 {%0,%1}, [%2];"
                 : "=r"(r[0]), "=r"(r[1]) : "r"(addr));
}
__device__ __forceinline__ void mma_bf16(float* d, const uint32_t* a, const uint32_t* b) {
    asm volatile(
        "mma.sync.aligned.m16n8k16.row.col.f32.bf16.bf16.f32 "
        "{%0,%1,%2,%3}, {%4,%5,%6,%7}, {%8,%9}, {%0,%1,%2,%3};"
        : "+f"(d[0]), "+f"(d[1]), "+f"(d[2]), "+f"(d[3])
        : "r"(a[0]), "r"(a[1]), "r"(a[2]), "r"(a[3]), "r"(b[0]), "r"(b[1]));
}
__device__ __forceinline__ void cp16(uint32_t saddr, const void* g) {
    asm volatile("cp.async.cg.shared.global [%0], [%1], 16;"
                 :: "r"(saddr), "l"(g) : "memory");
}
__device__ __forceinline__ float ex2(float x) {
    float r;
    asm("ex2.approx.ftz.f32 %0, %1;" : "=f"(r) : "f"(x));
    return r;
}
__device__ __forceinline__ void split2(float e0, float e1,
                                       uint32_t& hp_u, uint32_t& lp_u) {
    __nv_bfloat162 hp = __float22bfloat162_rn(make_float2(e0, e1));
    float h0 = __low2float(hp), h1 = __high2float(hp);
    __nv_bfloat162 lp = __float22bfloat162_rn(make_float2(e0 - h0, e1 - h1));
    hp_u = *reinterpret_cast<uint32_t*>(&hp);
    lp_u = *reinterpret_cast<uint32_t*>(&lp);
}

// ---------------------------------------------------------------------------
// Fused fp32 -> bf16 hi/lo split (one launch)
// ---------------------------------------------------------------------------
__global__ __launch_bounds__(256) void cvt_all(
    const float* __restrict__ X,  const float* __restrict__ Wq,
    const float* __restrict__ Wk, const float* __restrict__ Wv,
    const float* __restrict__ Wo)
{
    int b = blockIdx.x;
    const float* src;
    __nv_bfloat16 *hi, *lo;
    int base;
    if (b < 4096)       { src = X;  hi = g_Xh;  lo = g_Xl;  base = b; }
    else if (b < 8192)  { src = Wq; hi = g_Wqh; lo = g_Wql; base = b - 4096; }
    else if (b < 9216)  { src = Wk; hi = g_Wkh; lo = g_Wkl; base = b - 8192; }
    else if (b < 10240) { src = Wv; hi = g_Wvh; lo = g_Wvl; base = b - 9216; }
    else                { src = Wo; hi = g_Woh; lo = g_Wol; base = b - 10240; }

    int i = (base * 256 + threadIdx.x) * 4;
    float4 v = *(const float4*)(src + i);
    uint32_t h01, l01, h23, l23;
    split2(v.x, v.y, h01, l01);
    split2(v.z, v.w, h23, l23);
    uint32_t* hp = (uint32_t*)(hi + i);
    uint32_t* lp = (uint32_t*)(lo + i);
    hp[0] = h01; hp[1] = h23;
    lp[0] = l01; lp[1] = l23;
}

// ---------------------------------------------------------------------------
// Pipelined GEMM (R11 config): BK=64, 3-stage cp.async, SW128 XOR, 256 thr.
// ---------------------------------------------------------------------------
#define TILEB 16384
#define STAGEB 65536
#define GEMM_SMEM (3 * STAGEB)

extern __shared__ char dyn_smem[];

__device__ __forceinline__ void gemm_core(
    const __nv_bfloat16* __restrict__ gA0, const __nv_bfloat16* __restrict__ gA1,
    const __nv_bfloat16* __restrict__ gB0, const __nv_bfloat16* __restrict__ gB1,
    int K, uint32_t smb, float (&acc)[4][4][4])
{
    const int tid = threadIdx.x;
    const int wid = tid >> 5;
    const int lane = tid & 31;
    const int wm = wid >> 2;
    const int wn = wid & 3;

    const __nv_bfloat16* gT[4] = { gA0, gA1, gB0, gB1 };
    const int ldRow = tid >> 3;
    const int ldC   = tid & 7;
    const int nk = K / 64;

    auto issue = [&](int kc, int stg) {
        uint32_t sb = smb + stg * STAGEB;
#pragma unroll
        for (int t = 0; t < 4; t++) {
#pragma unroll
            for (int p = 0; p < 4; p++) {
                int row = ldRow + p * 32;
                int sw = ldC ^ (row & 7);
                cp16(sb + t * TILEB + row * 128 + sw * 16,
                     gT[t] + (size_t)row * K + kc * 64 + ldC * 8);
            }
        }
        asm volatile("cp.async.commit_group;" ::: "memory");
    };

    issue(0, 0);
    issue(1, 1);

    for (int kc = 0; kc < nk; kc++) {
        if (kc + 1 < nk)
            asm volatile("cp.async.wait_group 1;" ::: "memory");
        else
            asm volatile("cp.async.wait_group 0;" ::: "memory");
        __syncthreads();
        if (kc + 2 < nk) issue(kc + 2, (kc + 2) % 3);

        const uint32_t sb = smb + (kc % 3) * STAGEB;
#pragma unroll
        for (int ks = 0; ks < 4; ks++) {
            uint32_t bH[4][2], bL[4][2];
#pragma unroll
            for (int nt = 0; nt < 4; nt++) {
                int row = wn * 32 + nt * 8 + (lane & 7);
                int ch = ks * 2 + ((lane >> 3) & 1);
                uint32_t ba = sb + 2 * TILEB + row * 128 + ((ch ^ (row & 7)) * 16);
                ldm_x2(bH[nt], ba);
                ldm_x2(bL[nt], ba + TILEB);
            }
#pragma unroll
            for (int mt = 0; mt < 4; mt++) {
                int row = wm * 64 + mt * 16 + (lane & 15);
                int ch = ks * 2 + ((lane >> 4) & 1);
                uint32_t aa = sb + row * 128 + ((ch ^ (row & 7)) * 16);
                uint32_t aH[4], aL[4];
                ldm_x4(aH, aa);
                ldm_x4(aL, aa + TILEB);
#pragma unroll
                for (int nt = 0; nt < 4; nt++) mma_bf16(acc[mt][nt], aH, bH[nt]);
#pragma unroll
                for (int nt = 0; nt < 4; nt++) mma_bf16(acc[mt][nt], aL, bH[nt]);
#pragma unroll
                for (int nt = 0; nt < 4; nt++) mma_bf16(acc[mt][nt], aH, bL[nt]);
            }
        }
    }
}

__device__ __forceinline__ void epi_split(
    float (&acc)[4][4][4], __nv_bfloat16* Ch, __nv_bfloat16* Cl,
    int r0, int c0, int N, float scale)
{
    const int lane = threadIdx.x & 31;
    const int wid = threadIdx.x >> 5;
    const int wm = wid >> 2, wn = wid & 3;
    const int cr = lane >> 2;
    const int cc = (lane & 3) * 2;
#pragma unroll
    for (int mt = 0; mt < 4; mt++) {
#pragma unroll
        for (int nt = 0; nt < 4; nt++) {
            size_t i0 = (size_t)(r0 + wm * 64 + mt * 16 + cr) * N
                      + c0 + wn * 32 + nt * 8 + cc;
            size_t i1 = i0 + 8 * (size_t)N;
#pragma unroll
            for (int half = 0; half < 2; half++) {
                size_t ix = half ? i1 : i0;
                float e0 = acc[mt][nt][half * 2 + 0] * scale;
                float e1 = acc[mt][nt][half * 2 + 1] * scale;
                uint32_t hp, lp;
                split2(e0, e1, hp, lp);
                *(uint32_t*)(Ch + ix) = hp;
                *(uint32_t*)(Cl + ix) = lp;
            }
        }
    }
}

__global__ __launch_bounds__(256, 1) void gemm_qkv()
{
    const uint32_t smb = smem_u32(dyn_smem);
    const int bx = blockIdx.x;
    const int r0 = blockIdx.y * 128;

    const __nv_bfloat16 *Bh, *Bl;
    __nv_bfloat16 *Ch, *Cl;
    int N, c0;
    float scale;
    if (bx < 16)      { Bh = g_Wqh; Bl = g_Wql; Ch = g_qh; Cl = g_ql; N = HIDDEN; c0 = bx * 128;       scale = QSCALE; }
    else if (bx < 20) { Bh = g_Wkh; Bl = g_Wkl; Ch = g_kh; Cl = g_kl; N = KV_W;  c0 = (bx - 16) * 128; scale = 1.f; }
    else              { Bh = g_Wvh; Bl = g_Wvl; Ch = g_vh; Cl = g_vl; N = KV_W;  c0 = (bx - 20) * 128; scale = 1.f; }

    float acc[4][4][4];
#pragma unroll
    for (int i = 0; i < 4; i++)
#pragma unroll
        for (int j = 0; j < 4; j++)
#pragma unroll
            for (int e = 0; e < 4; e++) acc[i][j][e] = 0.f;

    gemm_core(g_Xh + (size_t)r0 * HIDDEN, g_Xl + (size_t)r0 * HIDDEN,
              Bh + (size_t)c0 * HIDDEN, Bl + (size_t)c0 * HIDDEN,
              HIDDEN, smb, acc);
    epi_split(acc, Ch, Cl, r0, c0, N, scale);
}

__global__ __launch_bounds__(256, 1) void gemm_oproj(float* __restrict__ Cf)
{
    const uint32_t smb = smem_u32(dyn_smem);
    const int r0 = blockIdx.y * 128;
    const int c0 = blockIdx.x * 128;

    float acc[4][4][4];
#pragma unroll
    for (int i = 0; i < 4; i++)
#pragma unroll
        for (int j = 0; j < 4; j++)
#pragma unroll
            for (int e = 0; e < 4; e++) acc[i][j][e] = 0.f;

    gemm_core(g_Ath + (size_t)r0 * HIDDEN, g_Atl + (size_t)r0 * HIDDEN,
              g_Woh + (size_t)c0 * HIDDEN, g_Wol + (size_t)c0 * HIDDEN,
              HIDDEN, smb, acc);

    const int lane = threadIdx.x & 31;
    const int wid = threadIdx.x >> 5;
    const int wm = wid >> 2, wn = wid & 3;
    const int cr = lane >> 2;
    const int cc = (lane & 3) * 2;
#pragma unroll
    for (int mt = 0; mt < 4; mt++) {
#pragma unroll
        for (int nt = 0; nt < 4; nt++) {
            float* base = Cf + (size_t)(r0 + wm * 64 + mt * 16 + cr) * HIDDEN
                             + c0 + wn * 32 + nt * 8 + cc;
            *(float2*)base = make_float2(acc[mt][nt][0], acc[mt][nt][1]);
            *(float2*)(base + 8 * (size_t)HIDDEN) =
                make_float2(acc[mt][nt][2], acc[mt][nt][3]);
        }
    }
}

// ---------------------------------------------------------------------------
// Flash attention: kv-tile = 128 keys (halved per-tile fixed costs),
// cp.async double-buffered, base-2 softmax, pre-scaled Q.
// smem (b16): Qh [0,9216), Ql [9216,18432),
//   KV stage = Kh(9216) Kl(9216) Vh(9216) Vl(9216) = 36864 elems (73728 B).
//   stage0 @18432, stage1 @55296. Total = 92160 elems = 184320 B.
// ---------------------------------------------------------------------------
#define SROW 72
#define QTILE 9216
#define KVTILE 9216
#define KVSTAGE 36864
#define FA_SMEM (92160 * 2)   // 184320 B

__global__ __launch_bounds__(256, 1) void flash_attn_mma(
    const __nv_bfloat16* __restrict__ Qh_g, const __nv_bfloat16* __restrict__ Ql_g,
    const __nv_bfloat16* __restrict__ Kh_g, const __nv_bfloat16* __restrict__ Kl_g,
    const __nv_bfloat16* __restrict__ Vh_g, const __nv_bfloat16* __restrict__ Vl_g,
    __nv_bfloat16* __restrict__ Oh_g, __nv_bfloat16* __restrict__ Ol_g)
{
    __nv_bfloat16* sm = (__nv_bfloat16*)dyn_smem;
    const uint32_t smb = smem_u32(sm);

    const int tid  = threadIdx.x;
    const int wid  = tid >> 5;
    const int lane = tid & 31;
    const int qb = (int)gridDim.x - 1 - (int)blockIdx.x;  // heavy first
    const int hh = blockIdx.y;
    const int q0 = qb * 128;
    const int kvoff = (hh >> 2) * HD;

    const __nv_bfloat16* kvsrc[4] = { Kh_g, Kl_g, Vh_g, Vl_g };

    // KV stage loader: 4 tiles x 128 rows x 8 chunks = 4096 chunks, 16/thread
    auto issue_kv = [&](int jb) {
        const int k0 = jb * 128;
        const uint32_t sb = smb + (uint32_t)(QTILE * 2 + (jb & 1) * KVSTAGE) * 2;
#pragma unroll
        for (int p = 0; p < 16; p++) {
            int idx = tid + p * 256;
            int t = idx >> 10;
            int rem = idx & 1023;
            int r = rem >> 3;
            int c = rem & 7;
            cp16(sb + (uint32_t)(t * KVTILE + r * SROW + c * 8) * 2,
                 kvsrc[t] + (size_t)(k0 + r) * KV_W + kvoff + c * 8);
        }
        asm volatile("cp.async.commit_group;" ::: "memory");
    };

    // Q tiles (plain loads)
#pragma unroll
    for (int p = 0; p < 8; p++) {
        int idx = tid + p * 256;
        int t = idx >> 10;
        int rem = idx & 1023;
        int r = rem >> 3;
        int c = rem & 7;
        const __nv_bfloat16* src = (t ? Ql_g : Qh_g) +
            (size_t)(q0 + r) * HIDDEN + hh * HD + c * 8;
        uint4 d = *(const uint4*)src;
        *(uint4*)(sm + (t ? QTILE : 0) + r * SROW + c * 8) = d;
    }

    float o[8][4];
#pragma unroll
    for (int nt = 0; nt < 8; nt++)
#pragma unroll
        for (int e = 0; e < 4; e++) o[nt][e] = 0.f;
    float m0 = -1e30f, m1 = -1e30f, l0 = 0.f, l1 = 0.f;

    const int cr = lane >> 2;
    const int cc = (lane & 3) * 2;
    const int row0 = q0 + wid * 16 + cr;
    const int row1 = row0 + 8;

    const uint32_t aHq = smb + (uint32_t)(
        (wid * 16 + (lane & 15)) * SROW + ((lane >> 4) & 1) * 8) * 2;
    const uint32_t aLq = aHq + (uint32_t)QTILE * 2;
    const uint32_t bKoff = (uint32_t)((lane & 7) * SROW + ((lane >> 3) & 1) * 8) * 2;
    const uint32_t bVoff = (uint32_t)(((lane & 7) + ((lane >> 3) & 1) * 8) * SROW) * 2;

    const int nkv = qb + 1;          // kv tiles of 128
    issue_kv(0);
    if (nkv > 1) issue_kv(1);

    for (int jb = 0; jb < nkv; jb++) {
        const int k0 = jb * 128;
        if (jb + 1 < nkv)
            asm volatile("cp.async.wait_group 1;" ::: "memory");
        else
            asm volatile("cp.async.wait_group 0;" ::: "memory");
        __syncthreads();

        const uint32_t stb = smb + (uint32_t)(QTILE * 2 + (jb & 1) * KVSTAGE) * 2;
        const uint32_t bK = stb + bKoff;
        const uint32_t bV = stb + (uint32_t)(2 * KVTILE) * 2 + bVoff;

        // ---- S = Q K^T over 128 keys ----
        float s[16][4];
#pragma unroll
        for (int nt = 0; nt < 16; nt++)
#pragma unroll
            for (int e = 0; e < 4; e++) s[nt][e] = 0.f;

#pragma unroll
        for (int ks = 0; ks < 4; ks++) {
            uint32_t aH[4], aL[4];
            ldm_x4(aH, aHq + ks * 32);
            ldm_x4(aL, aLq + ks * 32);
#pragma unroll
            for (int nt = 0; nt < 16; nt++) {
                uint32_t bh[2], bl[2];
                uint32_t ba = bK + (uint32_t)(nt * 8 * SROW) * 2 + ks * 32;
                ldm_x2(bh, ba);
                ldm_x2(bl, ba + (uint32_t)KVTILE * 2);
                mma_bf16(s[nt], aH, bh);
                mma_bf16(s[nt], aL, bh);
                mma_bf16(s[nt], aH, bl);
            }
        }

        // ---- causal mask (only diagonal tile) ----
        if (k0 + 127 > q0) {
#pragma unroll
            for (int nt = 0; nt < 16; nt++) {
                int col = k0 + nt * 8 + cc;
                if (col > row0)     s[nt][0] = -1e30f;
                if (col + 1 > row0) s[nt][1] = -1e30f;
                if (col > row1)     s[nt][2] = -1e30f;
                if (col + 1 > row1) s[nt][3] = -1e30f;
            }
        }

        // ---- online softmax (base-2) ----
        float mx0 = -1e30f, mx1 = -1e30f;
#pragma unroll
        for (int nt = 0; nt < 16; nt++) {
            mx0 = fmaxf(mx0, fmaxf(s[nt][0], s[nt][1]));
            mx1 = fmaxf(mx1, fmaxf(s[nt][2], s[nt][3]));
        }
        mx0 = fmaxf(mx0, __shfl_xor_sync(0xffffffffu, mx0, 1));
        mx0 = fmaxf(mx0, __shfl_xor_sync(0xffffffffu, mx0, 2));
        mx1 = fmaxf(mx1, __shfl_xor_sync(0xffffffffu, mx1, 1));
        mx1 = fmaxf(mx1, __shfl_xor_sync(0xffffffffu, mx1, 2));

        float m0n = fmaxf(m0, mx0);
        float m1n = fmaxf(m1, mx1);

        float sum0 = 0.f, sum1 = 0.f;
#pragma unroll
        for (int nt = 0; nt < 16; nt++) {
            s[nt][0] = ex2(s[nt][0] - m0n);
            s[nt][1] = ex2(s[nt][1] - m0n);
            s[nt][2] = ex2(s[nt][2] - m1n);
            s[nt][3] = ex2(s[nt][3] - m1n);
            sum0 += s[nt][0] + s[nt][1];
            sum1 += s[nt][2] + s[nt][3];
        }
        sum0 += __shfl_xor_sync(0xffffffffu, sum0, 1);
        sum0 += __shfl_xor_sync(0xffffffffu, sum0, 2);
        sum1 += __shfl_xor_sync(0xffffffffu, sum1, 1);
        sum1 += __shfl_xor_sync(0xffffffffu, sum1, 2);

        float sc0 = ex2(m0 - m0n);
        float sc1 = ex2(m1 - m1n);
        l0 = l0 * sc0 + sum0;
        l1 = l1 * sc1 + sum1;
        m0 = m0n; m1 = m1n;

#pragma unroll
        for (int nt = 0; nt < 8; nt++) {
            o[nt][0] *= sc0; o[nt][1] *= sc0;
            o[nt][2] *= sc1; o[nt][3] *= sc1;
        }

        // ---- P V over 128 keys (8 k-steps) ----
#pragma unroll
        for (int ks = 0; ks < 8; ks++) {
            uint32_t aP[4], aPl[4];
#pragma unroll
            for (int half = 0; half < 2; half++) {
                int nt = 2 * ks + half;
                split2(s[nt][0], s[nt][1], aP[half * 2 + 0], aPl[half * 2 + 0]);
                split2(s[nt][2], s[nt][3], aP[half * 2 + 1], aPl[half * 2 + 1]);
            }
#pragma unroll
            for (int nt = 0; nt < 8; nt++) {
                uint32_t bh[2], bl[2];
                uint32_t ba = bV + (uint32_t)(ks * 16 * SROW + nt * 8) * 2;
                ldm_x2t(bh, ba);
                ldm_x2t(bl, ba + (uint32_t)KVTILE * 2);
                mma_bf16(o[nt], aP,  bh);
                mma_bf16(o[nt], aPl, bh);
                mma_bf16(o[nt], aP,  bl);
            }
        }

        __syncthreads();
        if (jb + 2 < nkv) issue_kv(jb + 2);
    }

    // ---- normalize + store bf16 hi/lo ----
    float inv0 = 1.f / l0;
    float inv1 = 1.f / l1;
#pragma unroll
    for (int nt = 0; nt < 8; nt++) {
        size_t i0 = (size_t)row0 * HIDDEN + hh * HD + nt * 8 + cc;
        size_t i1 = (size_t)row1 * HIDDEN + hh * HD + nt * 8 + cc;
        uint32_t hp0, lp0, hp1, lp1;
        split2(o[nt][0] * inv0, o[nt][1] * inv0, hp0, lp0);
        split2(o[nt][2] * inv1, o[nt][3] * inv1, hp1, lp1);
        *(uint32_t*)(Oh_g + i0) = hp0;
        *(uint32_t*)(Oh_g + i1) = hp1;
        *(uint32_t*)(Ol_g + i0) = lp0;
        *(uint32_t*)(Ol_g + i1) = lp1;
    }
}

// ---------------------------------------------------------------------------
// kernel_launch
// ---------------------------------------------------------------------------
extern "C" void kernel_launch(void* const* d_in, const int* in_sizes, int n_in,
                              void* d_out, int out_size)
{
    const float* X  = (const float*)d_in[0];
    const float* Wq = (const float*)d_in[2];
    const float* Wk = (const float*)d_in[3];
    const float* Wv = (const float*)d_in[4];
    const float* Wo = (const float*)d_in[5];
    float* out = (float*)d_out;

    __nv_bfloat16 *qh, *ql, *kh, *kl, *vh, *vl, *Ath, *Atl;
    cudaGetSymbolAddress((void**)&qh, g_qh);   cudaGetSymbolAddress((void**)&ql, g_ql);
    cudaGetSymbolAddress((void**)&kh, g_kh);   cudaGetSymbolAddress((void**)&kl, g_kl);
    cudaGetSymbolAddress((void**)&vh, g_vh);   cudaGetSymbolAddress((void**)&vl, g_vl);
    cudaGetSymbolAddress((void**)&Ath, g_Ath); cudaGetSymbolAddress((void**)&Atl, g_Atl);

    cvt_all<<<14336, 256>>>(X, Wq, Wk, Wv, Wo);

    cudaFuncSetAttribute(gemm_qkv, cudaFuncAttributeMaxDynamicSharedMemorySize, GEMM_SMEM);
    cudaFuncSetAttribute(gemm_oproj, cudaFuncAttributeMaxDynamicSharedMemorySize, GEMM_SMEM);

    gemm_qkv<<<dim3(24, 16), 256, GEMM_SMEM>>>();

    cudaFuncSetAttribute(flash_attn_mma, cudaFuncAttributeMaxDynamicSharedMemorySize, FA_SMEM);
    flash_attn_mma<<<dim3(S_LEN / 128, NH), 256, FA_SMEM>>>(
        qh, ql, kh, kl, vh, vl, Ath, Atl);

    gemm_oproj<<<dim3(16, 16), 256, GEMM_SMEM>>>(out);
}